// round 6
// baseline (speedup 1.0000x reference)
#include <cuda_runtime.h>
#include <cstdint>
#include <cub/cub.cuh>

// ---------------- problem constants ----------------
#define CIN   512
#define NPX   10000           // 100*100
#define NA    9
#define NS    90000           // NPX*NA
#define TOPK  10000
#define NMSW  157             // ceil(TOPK/64)
#define POSTK 2000
#define IMG   1600.0f
#define STRIDE 16.0f
#define XCLIP 4.135166556742356f  // log(1000/16)
#define NMSTHR 0.7f

// ---------------- static device scratch ----------------
__device__ float g_rpn[CIN * NPX];                 // 20 MB
__device__ float g_wt[4608 * CIN];                 // 9.4 MB  W transposed [r][co]
__device__ float2 g_fdup[(size_t)CIN * NPX];       // 41 MB   feat duplicated (v,v)
__device__ float g_scores[NS];
__device__ int   g_sidx[NS];
__device__ float g_scores_s[NS];
__device__ int   g_sidx_s[NS];
__device__ float g_deltas[NS * 4];
__device__ float g_bx1[TOPK], g_by1[TOPK], g_bx2[TOPK], g_by2[TOPK];
__device__ float g_bar[TOPK], g_bsc[TOPK];
__device__ unsigned long long g_mask[(size_t)TOPK * NMSW];  // 12.56 MB
__device__ int   g_keep[POSTK];
__device__ __align__(256) unsigned char g_cubtmp[8u << 20];

// ---------------- f32x2 packed helpers ----------------
__device__ __forceinline__ unsigned long long ffma2(unsigned long long a,
                                                    unsigned long long b,
                                                    unsigned long long c)
{
    unsigned long long d;
    asm("fma.rn.f32x2 %0, %1, %2, %3;" : "=l"(d) : "l"(a), "l"(b), "l"(c));
    return d;
}
__device__ __forceinline__ void unpack_f32x2(unsigned long long v, float& lo, float& hi)
{
    unsigned int a, b;
    asm("mov.b64 {%0, %1}, %2;" : "=r"(a), "=r"(b) : "l"(v));
    lo = __uint_as_float(a);
    hi = __uint_as_float(b);
}

// ---------------- cp.async helpers ----------------
__device__ __forceinline__ unsigned int smem_u32(const void* p)
{
    return (unsigned int)__cvta_generic_to_shared(p);
}
__device__ __forceinline__ void cpa16(unsigned int dst, const void* src, int src_bytes)
{
    asm volatile("cp.async.cg.shared.global [%0], [%1], 16, %2;"
                 :: "r"(dst), "l"(src), "r"(src_bytes));
}
__device__ __forceinline__ void cpa_commit()
{
    asm volatile("cp.async.commit_group;");
}

// ---------------- pre-pass kernels ----------------
__global__ void noop_kernel() {}

// W[co][r] -> g_wt[r][co], r = ci*9+k
__global__ void wtrans_kernel(const float* __restrict__ Wc)
{
    int idx = blockIdx.x * 256 + threadIdx.x;           // 4608*512 elems
    if (idx >= 4608 * CIN) return;
    int r = idx >> 9, co = idx & 511;
    g_wt[idx] = Wc[(size_t)co * 4608 + r];
}

// feat -> duplicated float2 (v, v)
__global__ void fdup_kernel(const float* __restrict__ feat)
{
    size_t idx = (size_t)blockIdx.x * 256 + threadIdx.x;  // 5.12M elems
    if (idx >= (size_t)CIN * NPX) return;
    float v = feat[idx];
    g_fdup[idx] = make_float2(v, v);
}

// ---------------- conv1: 3x3, 512->512, pad 1, ReLU ------------------------
// Block tile: 32 co x 128 px; 256 threads (8 warps = 8 co-groups of 4 co);
// thread = 4 co x 4 consecutive px. All feat operands are pre-duplicated
// f32x2 pairs from smem; weights broadcast per warp (one LDS.128 per kx).
// 72-term fp32 chunks (8ci x 9 taps, (ci,ky,kx) ascending) flushed to fp64
// masters -- bit-identical numerics to the validated round-3/4/5 kernels.
#define FSP      336                 // halo dup-pairs per ci: [px0-104, px0+232)
#define F_CHUNK  (8 * FSP)           // 2688 pairs (8B each)
#define W_CHUNK  (72 * 32)           // 2304 floats
#define CONV1_SMEM ((2 * F_CHUNK) * 8 + (2 * W_CHUNK) * 4)   // 43008+18432=61440 B

__global__ __launch_bounds__(256, 2)
void conv1_kernel(const float* __restrict__ bc)
{
    extern __shared__ char smraw[];
    unsigned long long* fbuf[2] = {
        (unsigned long long*)smraw,
        (unsigned long long*)smraw + F_CHUNK };
    float* wbuf[2] = {
        (float*)(smraw + 2 * F_CHUNK * 8),
        (float*)(smraw + 2 * F_CHUNK * 8) + W_CHUNK };

    const int tid  = threadIdx.x;
    const int lane = tid & 31;
    const int wid  = tid >> 5;           // co-group 0..7
    const int px0  = blockIdx.x * 128;
    const int cob  = blockIdx.y * 32;
    const int cobase = cob + wid * 4;
    const int p0   = px0 + 4 * lane;     // first of 4 consecutive pixels
    const int x0   = p0 % 100;
    const bool edgeL = (x0 == 0);        // window[-1] wraps from prev row
    const bool edgeR = (x0 == 96);       // window[+4] wraps to next row
    const int o0   = 104 + 4 * lane;     // window base pair-index in fbuf row

    double acc[4][4];
    #pragma unroll
    for (int c = 0; c < 4; c++)
        #pragma unroll
        for (int u = 0; u < 4; u++) acc[c][u] = 0.0;

    // ---- async stage of one 8-ci chunk into buffer s ----
    auto stage = [&](int s, int ci0) {
        unsigned long long* fd = fbuf[s];
        float* wd = wbuf[s];
        // weights: rows r = ci0*9 .. +71, co slice [cob, cob+32): 576 cpa16
        {
            const float* src0 = g_wt + (size_t)(ci0 * 9) * CIN + cob;
            for (int t = tid; t < 576; t += 256) {
                int r = t >> 3, q = t & 7;
                cpa16(smem_u32(&wd[r * 32 + q * 4]), src0 + (size_t)r * CIN + q * 4, 16);
            }
        }
        // feat dup halo: 8 ci x 336 pairs, staged as 16B (=2 pairs): 1344 cpa16
        {
            for (int t = tid; t < 8 * 168; t += 256) {
                int ci = t / 168, oq = t - ci * 168;
                int o = 2 * oq;
                int g = px0 - 104 + o;
                int ok = (g >= 0 && g < NPX) ? 16 : 0;
                const float2* src = &g_fdup[(size_t)(ci0 + ci) * NPX + (ok ? g : 0)];
                cpa16(smem_u32(&fd[ci * FSP + o]), src, ok);
            }
        }
        cpa_commit();
    };

    stage(0, 0);

    for (int cch = 0; cch < 64; cch++) {
        const int cur = cch & 1;
        if (cch + 1 < 64) {
            stage(cur ^ 1, (cch + 1) * 8);
            asm volatile("cp.async.wait_group 1;");
        } else {
            asm volatile("cp.async.wait_group 0;");
        }
        __syncthreads();

        const unsigned long long* fd = fbuf[cur];
        const float* wd = wbuf[cur];

        // chunk accumulators: 2 co-pairs x 4 px, packed f32x2
        unsigned long long ch[2][4];
        #pragma unroll
        for (int c2 = 0; c2 < 2; c2++)
            #pragma unroll
            for (int u = 0; u < 4; u++) ch[c2][u] = 0ULL;

        #pragma unroll
        for (int ci = 0; ci < 8; ci++) {
            const unsigned long long* fci = fd + ci * FSP;
            #pragma unroll
            for (int ky = 0; ky < 3; ky++) {
                const unsigned long long* fw = fci + (ky - 1) * 100 + o0;
                unsigned long long wm1 = fw[-1];
                ulonglong2 b01 = *(const ulonglong2*)&fw[0];   // w0, w1
                ulonglong2 b23 = *(const ulonglong2*)&fw[2];   // w2, w3
                unsigned long long w4 = fw[4];
                if (edgeL) wm1 = 0ULL;
                if (edgeR) w4  = 0ULL;

                const float* wrow = wd + (ci * 9 + ky * 3) * 32 + wid * 4;
                // kx = 0: f(u) = window[u-1]
                {
                    ulonglong2 wv = *(const ulonglong2*)&wrow[0];
                    ch[0][0] = ffma2(wv.x, wm1,   ch[0][0]);
                    ch[1][0] = ffma2(wv.y, wm1,   ch[1][0]);
                    ch[0][1] = ffma2(wv.x, b01.x, ch[0][1]);
                    ch[1][1] = ffma2(wv.y, b01.x, ch[1][1]);
                    ch[0][2] = ffma2(wv.x, b01.y, ch[0][2]);
                    ch[1][2] = ffma2(wv.y, b01.y, ch[1][2]);
                    ch[0][3] = ffma2(wv.x, b23.x, ch[0][3]);
                    ch[1][3] = ffma2(wv.y, b23.x, ch[1][3]);
                }
                // kx = 1: f(u) = window[u]
                {
                    ulonglong2 wv = *(const ulonglong2*)&wrow[32];
                    ch[0][0] = ffma2(wv.x, b01.x, ch[0][0]);
                    ch[1][0] = ffma2(wv.y, b01.x, ch[1][0]);
                    ch[0][1] = ffma2(wv.x, b01.y, ch[0][1]);
                    ch[1][1] = ffma2(wv.y, b01.y, ch[1][1]);
                    ch[0][2] = ffma2(wv.x, b23.x, ch[0][2]);
                    ch[1][2] = ffma2(wv.y, b23.x, ch[1][2]);
                    ch[0][3] = ffma2(wv.x, b23.y, ch[0][3]);
                    ch[1][3] = ffma2(wv.y, b23.y, ch[1][3]);
                }
                // kx = 2: f(u) = window[u+1]
                {
                    ulonglong2 wv = *(const ulonglong2*)&wrow[64];
                    ch[0][0] = ffma2(wv.x, b01.y, ch[0][0]);
                    ch[1][0] = ffma2(wv.y, b01.y, ch[1][0]);
                    ch[0][1] = ffma2(wv.x, b23.x, ch[0][1]);
                    ch[1][1] = ffma2(wv.y, b23.x, ch[1][1]);
                    ch[0][2] = ffma2(wv.x, b23.y, ch[0][2]);
                    ch[1][2] = ffma2(wv.y, b23.y, ch[1][2]);
                    ch[0][3] = ffma2(wv.x, w4,    ch[0][3]);
                    ch[1][3] = ffma2(wv.y, w4,    ch[1][3]);
                }
            }
        }

        // flush 72-term fp32 chunks into fp64 masters
        #pragma unroll
        for (int c2 = 0; c2 < 2; c2++)
            #pragma unroll
            for (int u = 0; u < 4; u++) {
                float lo, hi;
                unpack_f32x2(ch[c2][u], lo, hi);
                acc[2 * c2 + 0][u] += (double)lo;
                acc[2 * c2 + 1][u] += (double)hi;
            }
        __syncthreads();
    }

    if (p0 < NPX) {   // p0 multiple of 4, NPX multiple of 4 -> p0+3 valid
        #pragma unroll
        for (int c = 0; c < 4; c++) {
            double b = (double)bc[cobase + c];
            float4 v;
            v.x = fmaxf((float)(acc[c][0] + b), 0.0f);
            v.y = fmaxf((float)(acc[c][1] + b), 0.0f);
            v.z = fmaxf((float)(acc[c][2] + b), 0.0f);
            v.w = fmaxf((float)(acc[c][3] + b), 0.0f);
            *(float4*)&g_rpn[(size_t)(cobase + c) * NPX + p0] = v;
        }
    }
}

// ---------------- conv2: 1x1 heads, fp64 accumulation ----------------------
__global__ __launch_bounds__(160)
void conv2_kernel(const float* __restrict__ Wcls, const float* __restrict__ bcls,
                  const float* __restrict__ Wbb,  const float* __restrict__ bbb)
{
    __shared__ float ws[45 * 128];
    const int tid  = threadIdx.x;
    const int cg   = tid >> 5;    // 0..4
    const int lane = tid & 31;
    const int px0  = blockIdx.x * 64;

    int gp[2];
    #pragma unroll
    for (int u = 0; u < 2; u++) gp[u] = px0 + lane + 32 * u;

    double acc[9][2];
    #pragma unroll
    for (int c = 0; c < 9; c++)
        #pragma unroll
        for (int u = 0; u < 2; u++) acc[c][u] = 0.0;

    for (int ci0 = 0; ci0 < CIN; ci0 += 128) {
        __syncthreads();
        for (int t = tid; t < 45 * 128; t += 160) {
            int c = t >> 7, o = t & 127;
            ws[t] = (c < 9) ? Wcls[c * CIN + ci0 + o] : Wbb[(c - 9) * CIN + ci0 + o];
        }
        __syncthreads();
        for (int ci = 0; ci < 128; ci++) {
            const float* rp = &g_rpn[(size_t)(ci0 + ci) * NPX];
            double f[2];
            #pragma unroll
            for (int u = 0; u < 2; u++)
                f[u] = (gp[u] < NPX) ? (double)rp[gp[u]] : 0.0;
            #pragma unroll
            for (int c9 = 0; c9 < 9; c9++) {
                double w = (double)ws[(cg * 9 + c9) * 128 + ci];
                #pragma unroll
                for (int u = 0; u < 2; u++)
                    acc[c9][u] = fma(w, f[u], acc[c9][u]);
            }
        }
    }

    #pragma unroll
    for (int u = 0; u < 2; u++) {
        if (gp[u] >= NPX) continue;
        int p = gp[u];
        if (cg == 0) {
            #pragma unroll
            for (int a = 0; a < 9; a++) {
                float xl = (float)(acc[a][u] + (double)bcls[a]);
                // XLA LogisticExpander: logistic(x) = 0.5 + 0.5*tanh(0.5*x)
                float sc = 0.5f + 0.5f * tanhf(0.5f * xl);
                int si = p * 9 + a;
                g_scores[si] = sc;
                g_sidx[si]   = si;
            }
        } else {
            #pragma unroll
            for (int c9 = 0; c9 < 9; c9++) {
                int cc = (cg - 1) * 9 + c9;       // bbox channel 0..35
                int a = cc >> 2, comp = cc & 3;
                float v = (float)(acc[c9][u] + (double)bbb[cc]);
                g_deltas[(size_t)(p * 9 + a) * 4 + comp] = v;
            }
        }
    }
}

// ---------------- decode top-10000 boxes ----------------
__global__ void decode_kernel()
{
    int i = blockIdx.x * 256 + threadIdx.x;
    if (i >= TOPK) return;
    int idx  = g_sidx_s[i];
    float sc = g_scores_s[i];
    int a = idx % 9;
    int p = idx / 9;
    int x = p % 100, y = p / 100;

    int r = a / 3, s = a % 3;
    float ratio = (r == 0) ? 0.5f : (r == 1) ? 1.0f : 2.0f;
    float scale = (s == 0) ? 128.0f : (s == 1) ? 256.0f : 512.0f;
    float hr = sqrtf(ratio);
    float wr = 1.0f / hr;
    float ws = wr * scale, hs = hr * scale;

    float ax1 = x * STRIDE + rintf(-ws * 0.5f);
    float ay1 = y * STRIDE + rintf(-hs * 0.5f);
    float ax2 = x * STRIDE + rintf( ws * 0.5f);
    float ay2 = y * STRIDE + rintf( hs * 0.5f);

    float w  = ax2 - ax1;
    float h  = ay2 - ay1;
    float cx = ax1 + 0.5f * w;
    float cy = ay1 + 0.5f * h;

    const float4 dl = *reinterpret_cast<const float4*>(&g_deltas[(size_t)idx * 4]);
    float dx = dl.x, dy = dl.y;
    float dw = fminf(dl.z, XCLIP);
    float dh = fminf(dl.w, XCLIP);

    float pcx = dx * w + cx;
    float pcy = dy * h + cy;
    float pw  = expf(dw) * w;
    float ph  = expf(dh) * h;

    float x1 = fminf(fmaxf(pcx - 0.5f * pw, 0.0f), IMG);
    float y1 = fminf(fmaxf(pcy - 0.5f * ph, 0.0f), IMG);
    float x2 = fminf(fmaxf(pcx + 0.5f * pw, 0.0f), IMG);
    float y2 = fminf(fmaxf(pcy + 0.5f * ph, 0.0f), IMG);

    g_bx1[i] = x1; g_by1[i] = y1; g_bx2[i] = x2; g_by2[i] = y2;
    g_bar[i] = (x2 - x1) * (y2 - y1);
    g_bsc[i] = sc;
}

// ---------------- NMS bitmask ----------------
__global__ void nms_mask_kernel()
{
    const int bi = blockIdx.y, bj = blockIdx.x;
    const int t  = threadIdx.x;
    if (bj < bi) return;

    __shared__ float sx1[64], sy1[64], sx2[64], sy2[64], sa[64];
    int j0 = bj * 64;
    int j  = j0 + t;
    if (j < TOPK) {
        sx1[t] = g_bx1[j]; sy1[t] = g_by1[j];
        sx2[t] = g_bx2[j]; sy2[t] = g_by2[j];
        sa[t]  = g_bar[j];
    }
    __syncthreads();

    int i = bi * 64 + t;
    if (i >= TOPK) return;
    float bx1 = g_bx1[i], by1 = g_by1[i], bx2 = g_bx2[i], by2 = g_by2[i], ba = g_bar[i];

    unsigned long long bits = 0;
    int jmax = min(64, TOPK - j0);
    for (int jj = 0; jj < jmax; jj++) {
        int jg = j0 + jj;
        if (jg <= i) continue;
        float ix = fminf(bx2, sx2[jj]) - fmaxf(bx1, sx1[jj]);
        float iy = fminf(by2, sy2[jj]) - fmaxf(by1, sy1[jj]);
        ix = fmaxf(ix, 0.0f);
        iy = fmaxf(iy, 0.0f);
        float inter = ix * iy;
        float iou = inter / (ba + sa[jj] - inter);
        if (iou > NMSTHR) bits |= (1ULL << jj);
    }
    g_mask[(size_t)i * NMSW + bj] = bits;
}

// ---------------- greedy scan: smem diag prefetch + MLP OR-gather ----------
__global__ void nms_scan_kernel()
{
    __shared__ unsigned long long s_diag[64];
    __shared__ unsigned long long s_alive;
    __shared__ int s_cnt;
    const int t = threadIdx.x;            // 192 threads
    if (t == 0) s_cnt = 0;
    for (int j = t; j < POSTK; j += blockDim.x) g_keep[j] = 0;

    unsigned long long remv = 0;          // removal word owned by thread t

    for (int b = 0; b < NMSW; b++) {
        __syncthreads();
        int n = min(64, TOPK - b * 64);
        if (t < n) s_diag[t] = g_mask[(size_t)(b * 64 + t) * NMSW + b];
        __syncthreads();

        if (t == b) {
            unsigned long long w = remv;
            unsigned long long alive = 0;
            int cnt = s_cnt;
            for (int bit = 0; bit < n; bit++) {
                if (!((w >> bit) & 1ULL)) {
                    alive |= (1ULL << bit);
                    if (cnt < POSTK) g_keep[cnt++] = b * 64 + bit;
                    w |= s_diag[bit];
                }
            }
            s_cnt = cnt;
            s_alive = alive;
            remv = w;
        }
        __syncthreads();

        if (s_cnt >= POSTK) break;

        if (t < NMSW && t > b) {
            unsigned long long am = s_alive;
            while (am) {
                int b0, b1 = -1, b2 = -1, b3 = -1;
                b0 = __ffsll((long long)am) - 1; am &= am - 1;
                if (am) { b1 = __ffsll((long long)am) - 1; am &= am - 1; }
                if (am) { b2 = __ffsll((long long)am) - 1; am &= am - 1; }
                if (am) { b3 = __ffsll((long long)am) - 1; am &= am - 1; }
                unsigned long long v0 = g_mask[(size_t)(b * 64 + b0) * NMSW + t];
                unsigned long long v1 = (b1 >= 0) ? g_mask[(size_t)(b * 64 + b1) * NMSW + t] : 0ULL;
                unsigned long long v2 = (b2 >= 0) ? g_mask[(size_t)(b * 64 + b2) * NMSW + t] : 0ULL;
                unsigned long long v3 = (b3 >= 0) ? g_mask[(size_t)(b * 64 + b3) * NMSW + t] : 0ULL;
                remv |= (v0 | v1) | (v2 | v3);
            }
        }
    }
}

// ---------------- gather output [2000,5] ----------------
__global__ void output_kernel(float* __restrict__ out)
{
    int j = blockIdx.x * 256 + threadIdx.x;
    if (j >= POSTK) return;
    int k = g_keep[j];
    out[j * 5 + 0] = g_bx1[k];
    out[j * 5 + 1] = g_by1[k];
    out[j * 5 + 2] = g_bx2[k];
    out[j * 5 + 3] = g_by2[k];
    out[j * 5 + 4] = g_bsc[k];
}

// ---------------- host launch ----------------
extern "C" void kernel_launch(void* const* d_in, const int* in_sizes, int n_in,
                              void* d_out, int out_size)
{
    (void)in_sizes; (void)n_in; (void)out_size;
    const float* feat  = (const float*)d_in[1];
    const float* Wconv = (const float*)d_in[2];
    const float* bconv = (const float*)d_in[3];
    const float* Wcls  = (const float*)d_in[4];
    const float* bcls  = (const float*)d_in[5];
    const float* Wbb   = (const float*)d_in[6];
    const float* bbb   = (const float*)d_in[7];
    float* out = (float*)d_out;

    void *p_sc, *p_idx, *p_scs, *p_idxs, *p_tmp;
    cudaGetSymbolAddress(&p_sc,   g_scores);
    cudaGetSymbolAddress(&p_idx,  g_sidx);
    cudaGetSymbolAddress(&p_scs,  g_scores_s);
    cudaGetSymbolAddress(&p_idxs, g_sidx_s);
    cudaGetSymbolAddress(&p_tmp,  g_cubtmp);

    cudaFuncSetAttribute(conv1_kernel,
                         cudaFuncAttributeMaxDynamicSharedMemorySize,
                         CONV1_SMEM);

    // launches 0-4: pre-passes + padding so ncu (-s 5 -c 1) profiles conv1
    wtrans_kernel<<<(4608 * CIN + 255) / 256, 256>>>(Wconv);             // #0
    fdup_kernel<<<(int)(((size_t)CIN * NPX + 255) / 256), 256>>>(feat);  // #1
    noop_kernel<<<1, 32>>>();                                            // #2
    noop_kernel<<<1, 32>>>();                                            // #3
    noop_kernel<<<1, 32>>>();                                            // #4

    // conv1: 79 px-tiles x 16 co-tiles                                  // #5
    conv1_kernel<<<dim3(79, 16), 256, CONV1_SMEM>>>(bconv);
    conv2_kernel<<<157, 160>>>(Wcls, bcls, Wbb, bbb);

    size_t tmp_bytes = sizeof(g_cubtmp);
    cub::DeviceRadixSort::SortPairsDescending(
        p_tmp, tmp_bytes,
        (const float*)p_sc, (float*)p_scs,
        (const int*)p_idx,  (int*)p_idxs,
        NS, 0, 32, (cudaStream_t)0);

    decode_kernel<<<40, 256>>>();
    nms_mask_kernel<<<dim3(NMSW, NMSW), 64>>>();
    nms_scan_kernel<<<1, 192>>>();
    output_kernel<<<8, 256>>>(out);
}

// round 7
// speedup vs baseline: 1.5817x; 1.5817x over previous
#include <cuda_runtime.h>
#include <cstdint>
#include <cub/cub.cuh>

// ---------------- problem constants ----------------
#define CIN   512
#define NPX   10000           // 100*100
#define NA    9
#define NS    90000           // NPX*NA
#define TOPK  10000
#define NMSW  157             // ceil(TOPK/64)
#define POSTK 2000
#define IMG   1600.0f
#define STRIDE 16.0f
#define XCLIP 4.135166556742356f  // log(1000/16)
#define NMSTHR 0.7f

// ---------------- static device scratch ----------------
__device__ float g_rpn[CIN * NPX];                 // 20 MB
__device__ float g_wt[4608 * CIN];                 // 9.4 MB  W transposed [r][co]
__device__ float g_scores[NS];
__device__ int   g_sidx[NS];
__device__ float g_scores_s[NS];
__device__ int   g_sidx_s[NS];
__device__ float g_deltas[NS * 4];
__device__ float g_bx1[TOPK], g_by1[TOPK], g_bx2[TOPK], g_by2[TOPK];
__device__ float g_bar[TOPK], g_bsc[TOPK];
__device__ unsigned long long g_mask[(size_t)TOPK * NMSW];  // 12.56 MB
__device__ int   g_keep[POSTK];
__device__ __align__(256) unsigned char g_cubtmp[8u << 20];

// ---------------- f32x2 packed helpers ----------------
__device__ __forceinline__ unsigned long long ffma2(unsigned long long a,
                                                    unsigned long long b,
                                                    unsigned long long c)
{
    unsigned long long d;
    asm("fma.rn.f32x2 %0, %1, %2, %3;" : "=l"(d) : "l"(a), "l"(b), "l"(c));
    return d;
}
__device__ __forceinline__ unsigned long long dup_f32(float x)
{
    unsigned int u = __float_as_uint(x);
    unsigned long long d;
    asm("mov.b64 %0, {%1, %1};" : "=l"(d) : "r"(u));
    return d;
}
__device__ __forceinline__ void unpack_f32x2(unsigned long long v, float& lo, float& hi)
{
    unsigned int a, b;
    asm("mov.b64 {%0, %1}, %2;" : "=r"(a), "=r"(b) : "l"(v));
    lo = __uint_as_float(a);
    hi = __uint_as_float(b);
}

// ---------------- cp.async helpers ----------------
__device__ __forceinline__ unsigned int smem_u32(const void* p)
{
    return (unsigned int)__cvta_generic_to_shared(p);
}
__device__ __forceinline__ void cpa16(unsigned int dst, const void* src, int src_bytes)
{
    asm volatile("cp.async.cg.shared.global [%0], [%1], 16, %2;"
                 :: "r"(dst), "l"(src), "r"(src_bytes));
}
__device__ __forceinline__ void cpa_commit()
{
    asm volatile("cp.async.commit_group;");
}

// ---------------- pre-pass kernels ----------------
__global__ void noop_kernel() {}

// W[co][r] -> g_wt[r][co], r = ci*9+k
__global__ void wtrans_kernel(const float* __restrict__ Wc)
{
    int idx = blockIdx.x * 256 + threadIdx.x;           // 4608*512 elems
    if (idx >= 4608 * CIN) return;
    int r = idx >> 9, co = idx & 511;
    g_wt[idx] = Wc[(size_t)co * 4608 + r];
}

// ---------------- conv1: 3x3, 512->512, pad 1, ReLU ------------------------
// Block tile: 64 co x 128 px; 256 threads (8 warps = 8 co-groups of 8 co);
// thread = 8 co x 4 CONSECUTIVE px. Per (ci,ky): one 6-float window feeds all
// 3 kx taps of 4 pixels (3 smem loads + 2 edge zeros). fma.rn.f32x2 over
// (co,co+1) pairs. 72-term fp32 chunks (8ci x k=0..8 ascending) flushed to
// fp64 masters — bit-identical numerics to the validated round-3/4 kernels.
#define WS       68                  // weight smem row stride (64 co + 4 pad)
#define W_CHUNK  (72 * WS)           // 4896 floats
#define FS       336                 // halo floats per ci: [px0-104, px0+232)
#define F_CHUNK  (8 * FS)            // 2688 floats
#define CONV1_SMEM ((2 * W_CHUNK + 2 * F_CHUNK) * 4)   // 60,672 B

__global__ __launch_bounds__(256, 1)
void conv1_kernel(const float* __restrict__ feat,
                  const float* __restrict__ bc)
{
    extern __shared__ float sm[];
    float* wbuf[2] = { sm, sm + W_CHUNK };
    float* fbuf[2] = { sm + 2 * W_CHUNK, sm + 2 * W_CHUNK + F_CHUNK };

    const int tid  = threadIdx.x;
    const int lane = tid & 31;
    const int tco  = tid >> 5;           // co-group 0..7
    const int px0  = blockIdx.x * 128;
    const int cob  = blockIdx.y * 64;
    const int cobase = cob + tco * 8;
    const int p0   = px0 + 4 * lane;     // first of 4 consecutive pixels
    const int x0   = p0 % 100;
    const bool edgeL = (x0 == 0);        // window[-1] wraps from prev row
    const bool edgeR = (x0 == 96);       // window[+4] wraps to next row
    const int o0   = 104 + 4 * lane;     // p0's index within fbuf ci-row

    double acc[8][4];
    #pragma unroll
    for (int c = 0; c < 8; c++)
        #pragma unroll
        for (int u = 0; u < 4; u++) acc[c][u] = 0.0;

    // ---- async stage of one 8-ci chunk into buffer s ----
    auto stage = [&](int s, int ci0) {
        float* wd = wbuf[s];
        float* fd = fbuf[s];
        // weights: 72 rows (r = ci0*9 ..), co slice [cob, cob+64): 1152 cpa16
        for (int t = tid; t < 1152; t += 256) {
            int r = t >> 4, q = t & 15;
            cpa16(smem_u32(&wd[r * WS + q * 4]),
                  g_wt + (size_t)(ci0 * 9 + r) * CIN + cob + q * 4, 16);
        }
        // feat halo: 8 ci x 84 16B-groups; 4-aligned boundaries -> no straddle
        for (int t = tid; t < 672; t += 256) {
            int ci = t / 84, oq = t - ci * 84;
            int o = oq * 4;
            int g = px0 - 104 + o;
            int ok = (g >= 0 && g < NPX) ? 16 : 0;
            const float* src = feat + (size_t)(ci0 + ci) * NPX + (ok ? g : 0);
            cpa16(smem_u32(&fd[ci * FS + o]), src, ok);
        }
        cpa_commit();
    };

    stage(0, 0);

    for (int cch = 0; cch < 64; cch++) {
        const int cur = cch & 1;
        if (cch + 1 < 64) {
            stage(cur ^ 1, (cch + 1) * 8);
            asm volatile("cp.async.wait_group 1;");
        } else {
            asm volatile("cp.async.wait_group 0;");
        }
        __syncthreads();

        const float* wd = wbuf[cur];
        const float* fd = fbuf[cur];

        // chunk accumulators: 4 co-pairs x 4 px, packed f32x2
        unsigned long long ch[4][4];
        #pragma unroll
        for (int c2 = 0; c2 < 4; c2++)
            #pragma unroll
            for (int u = 0; u < 4; u++) ch[c2][u] = 0ULL;

        #pragma unroll
        for (int ci = 0; ci < 8; ci++) {
            const float* fb = fd + ci * FS + o0;
            #pragma unroll
            for (int ky = 0; ky < 3; ky++) {
                const float* bp = fb + (ky - 1) * 100;
                float wm1 = bp[-1];                       // window[-1]
                float4 w03 = *(const float4*)bp;          // window[0..3] (16B aligned)
                float w4  = bp[4];                        // window[4]
                if (edgeL) wm1 = 0.0f;
                if (edgeR) w4  = 0.0f;
                unsigned long long dm1 = dup_f32(wm1);
                unsigned long long d0  = dup_f32(w03.x);
                unsigned long long d1  = dup_f32(w03.y);
                unsigned long long d2  = dup_f32(w03.z);
                unsigned long long d3  = dup_f32(w03.w);
                unsigned long long d4  = dup_f32(w4);

                const float* wrow = wd + (ci * 9 + ky * 3) * WS + tco * 8;
                // kx = 0: f(u) = window[u-1]
                {
                    ulonglong2 wA = *(const ulonglong2*)&wrow[0];
                    ulonglong2 wB = *(const ulonglong2*)&wrow[4];
                    ch[0][0] = ffma2(wA.x, dm1, ch[0][0]);
                    ch[1][0] = ffma2(wA.y, dm1, ch[1][0]);
                    ch[2][0] = ffma2(wB.x, dm1, ch[2][0]);
                    ch[3][0] = ffma2(wB.y, dm1, ch[3][0]);
                    ch[0][1] = ffma2(wA.x, d0,  ch[0][1]);
                    ch[1][1] = ffma2(wA.y, d0,  ch[1][1]);
                    ch[2][1] = ffma2(wB.x, d0,  ch[2][1]);
                    ch[3][1] = ffma2(wB.y, d0,  ch[3][1]);
                    ch[0][2] = ffma2(wA.x, d1,  ch[0][2]);
                    ch[1][2] = ffma2(wA.y, d1,  ch[1][2]);
                    ch[2][2] = ffma2(wB.x, d1,  ch[2][2]);
                    ch[3][2] = ffma2(wB.y, d1,  ch[3][2]);
                    ch[0][3] = ffma2(wA.x, d2,  ch[0][3]);
                    ch[1][3] = ffma2(wA.y, d2,  ch[1][3]);
                    ch[2][3] = ffma2(wB.x, d2,  ch[2][3]);
                    ch[3][3] = ffma2(wB.y, d2,  ch[3][3]);
                }
                // kx = 1: f(u) = window[u]
                {
                    ulonglong2 wA = *(const ulonglong2*)&wrow[WS];
                    ulonglong2 wB = *(const ulonglong2*)&wrow[WS + 4];
                    ch[0][0] = ffma2(wA.x, d0, ch[0][0]);
                    ch[1][0] = ffma2(wA.y, d0, ch[1][0]);
                    ch[2][0] = ffma2(wB.x, d0, ch[2][0]);
                    ch[3][0] = ffma2(wB.y, d0, ch[3][0]);
                    ch[0][1] = ffma2(wA.x, d1, ch[0][1]);
                    ch[1][1] = ffma2(wA.y, d1, ch[1][1]);
                    ch[2][1] = ffma2(wB.x, d1, ch[2][1]);
                    ch[3][1] = ffma2(wB.y, d1, ch[3][1]);
                    ch[0][2] = ffma2(wA.x, d2, ch[0][2]);
                    ch[1][2] = ffma2(wA.y, d2, ch[1][2]);
                    ch[2][2] = ffma2(wB.x, d2, ch[2][2]);
                    ch[3][2] = ffma2(wB.y, d2, ch[3][2]);
                    ch[0][3] = ffma2(wA.x, d3, ch[0][3]);
                    ch[1][3] = ffma2(wA.y, d3, ch[1][3]);
                    ch[2][3] = ffma2(wB.x, d3, ch[2][3]);
                    ch[3][3] = ffma2(wB.y, d3, ch[3][3]);
                }
                // kx = 2: f(u) = window[u+1]
                {
                    ulonglong2 wA = *(const ulonglong2*)&wrow[2 * WS];
                    ulonglong2 wB = *(const ulonglong2*)&wrow[2 * WS + 4];
                    ch[0][0] = ffma2(wA.x, d1, ch[0][0]);
                    ch[1][0] = ffma2(wA.y, d1, ch[1][0]);
                    ch[2][0] = ffma2(wB.x, d1, ch[2][0]);
                    ch[3][0] = ffma2(wB.y, d1, ch[3][0]);
                    ch[0][1] = ffma2(wA.x, d2, ch[0][1]);
                    ch[1][1] = ffma2(wA.y, d2, ch[1][1]);
                    ch[2][1] = ffma2(wB.x, d2, ch[2][1]);
                    ch[3][1] = ffma2(wB.y, d2, ch[3][1]);
                    ch[0][2] = ffma2(wA.x, d3, ch[0][2]);
                    ch[1][2] = ffma2(wA.y, d3, ch[1][2]);
                    ch[2][2] = ffma2(wB.x, d3, ch[2][2]);
                    ch[3][2] = ffma2(wB.y, d3, ch[3][2]);
                    ch[0][3] = ffma2(wA.x, d4, ch[0][3]);
                    ch[1][3] = ffma2(wA.y, d4, ch[1][3]);
                    ch[2][3] = ffma2(wB.x, d4, ch[2][3]);
                    ch[3][3] = ffma2(wB.y, d4, ch[3][3]);
                }
            }
        }

        // flush 72-term fp32 chunks into fp64 masters
        #pragma unroll
        for (int c2 = 0; c2 < 4; c2++)
            #pragma unroll
            for (int u = 0; u < 4; u++) {
                float lo, hi;
                unpack_f32x2(ch[c2][u], lo, hi);
                acc[2 * c2 + 0][u] += (double)lo;
                acc[2 * c2 + 1][u] += (double)hi;
            }
        __syncthreads();
    }

    if (p0 < NPX) {   // p0 multiple of 4, NPX multiple of 4 -> p0+3 valid
        #pragma unroll
        for (int c = 0; c < 8; c++) {
            double b = (double)bc[cobase + c];
            float4 v;
            v.x = fmaxf((float)(acc[c][0] + b), 0.0f);
            v.y = fmaxf((float)(acc[c][1] + b), 0.0f);
            v.z = fmaxf((float)(acc[c][2] + b), 0.0f);
            v.w = fmaxf((float)(acc[c][3] + b), 0.0f);
            *(float4*)&g_rpn[(size_t)(cobase + c) * NPX + p0] = v;
        }
    }
}

// ---------------- conv2: 1x1 heads, fp64 accumulation ----------------------
__global__ __launch_bounds__(160)
void conv2_kernel(const float* __restrict__ Wcls, const float* __restrict__ bcls,
                  const float* __restrict__ Wbb,  const float* __restrict__ bbb)
{
    __shared__ float ws[45 * 128];
    const int tid  = threadIdx.x;
    const int cg   = tid >> 5;    // 0..4
    const int lane = tid & 31;
    const int px0  = blockIdx.x * 64;

    int gp[2];
    #pragma unroll
    for (int u = 0; u < 2; u++) gp[u] = px0 + lane + 32 * u;

    double acc[9][2];
    #pragma unroll
    for (int c = 0; c < 9; c++)
        #pragma unroll
        for (int u = 0; u < 2; u++) acc[c][u] = 0.0;

    for (int ci0 = 0; ci0 < CIN; ci0 += 128) {
        __syncthreads();
        for (int t = tid; t < 45 * 128; t += 160) {
            int c = t >> 7, o = t & 127;
            ws[t] = (c < 9) ? Wcls[c * CIN + ci0 + o] : Wbb[(c - 9) * CIN + ci0 + o];
        }
        __syncthreads();
        for (int ci = 0; ci < 128; ci++) {
            const float* rp = &g_rpn[(size_t)(ci0 + ci) * NPX];
            double f[2];
            #pragma unroll
            for (int u = 0; u < 2; u++)
                f[u] = (gp[u] < NPX) ? (double)rp[gp[u]] : 0.0;
            #pragma unroll
            for (int c9 = 0; c9 < 9; c9++) {
                double w = (double)ws[(cg * 9 + c9) * 128 + ci];
                #pragma unroll
                for (int u = 0; u < 2; u++)
                    acc[c9][u] = fma(w, f[u], acc[c9][u]);
            }
        }
    }

    #pragma unroll
    for (int u = 0; u < 2; u++) {
        if (gp[u] >= NPX) continue;
        int p = gp[u];
        if (cg == 0) {
            #pragma unroll
            for (int a = 0; a < 9; a++) {
                float xl = (float)(acc[a][u] + (double)bcls[a]);
                // XLA LogisticExpander: logistic(x) = 0.5 + 0.5*tanh(0.5*x)
                float sc = 0.5f + 0.5f * tanhf(0.5f * xl);
                int si = p * 9 + a;
                g_scores[si] = sc;
                g_sidx[si]   = si;
            }
        } else {
            #pragma unroll
            for (int c9 = 0; c9 < 9; c9++) {
                int cc = (cg - 1) * 9 + c9;       // bbox channel 0..35
                int a = cc >> 2, comp = cc & 3;
                float v = (float)(acc[c9][u] + (double)bbb[cc]);
                g_deltas[(size_t)(p * 9 + a) * 4 + comp] = v;
            }
        }
    }
}

// ---------------- decode top-10000 boxes ----------------
__global__ void decode_kernel()
{
    int i = blockIdx.x * 256 + threadIdx.x;
    if (i >= TOPK) return;
    int idx  = g_sidx_s[i];
    float sc = g_scores_s[i];
    int a = idx % 9;
    int p = idx / 9;
    int x = p % 100, y = p / 100;

    int r = a / 3, s = a % 3;
    float ratio = (r == 0) ? 0.5f : (r == 1) ? 1.0f : 2.0f;
    float scale = (s == 0) ? 128.0f : (s == 1) ? 256.0f : 512.0f;
    float hr = sqrtf(ratio);
    float wr = 1.0f / hr;
    float ws = wr * scale, hs = hr * scale;

    float ax1 = x * STRIDE + rintf(-ws * 0.5f);
    float ay1 = y * STRIDE + rintf(-hs * 0.5f);
    float ax2 = x * STRIDE + rintf( ws * 0.5f);
    float ay2 = y * STRIDE + rintf( hs * 0.5f);

    float w  = ax2 - ax1;
    float h  = ay2 - ay1;
    float cx = ax1 + 0.5f * w;
    float cy = ay1 + 0.5f * h;

    const float4 dl = *reinterpret_cast<const float4*>(&g_deltas[(size_t)idx * 4]);
    float dx = dl.x, dy = dl.y;
    float dw = fminf(dl.z, XCLIP);
    float dh = fminf(dl.w, XCLIP);

    float pcx = dx * w + cx;
    float pcy = dy * h + cy;
    float pw  = expf(dw) * w;
    float ph  = expf(dh) * h;

    float x1 = fminf(fmaxf(pcx - 0.5f * pw, 0.0f), IMG);
    float y1 = fminf(fmaxf(pcy - 0.5f * ph, 0.0f), IMG);
    float x2 = fminf(fmaxf(pcx + 0.5f * pw, 0.0f), IMG);
    float y2 = fminf(fmaxf(pcy + 0.5f * ph, 0.0f), IMG);

    g_bx1[i] = x1; g_by1[i] = y1; g_bx2[i] = x2; g_by2[i] = y2;
    g_bar[i] = (x2 - x1) * (y2 - y1);
    g_bsc[i] = sc;
}

// ---------------- NMS bitmask: 256 threads = 4 i-words per block -----------
__global__ void nms_mask_kernel()
{
    const int bj  = blockIdx.x;
    const int sub = threadIdx.x >> 6;            // 0..3
    const int t   = threadIdx.x & 63;
    const int bi  = blockIdx.y * 4 + sub;

    __shared__ float sx1[64], sy1[64], sx2[64], sy2[64], sa[64];
    int j0 = bj * 64;
    if (threadIdx.x < 64) {
        int j = j0 + threadIdx.x;
        if (j < TOPK) {
            sx1[threadIdx.x] = g_bx1[j]; sy1[threadIdx.x] = g_by1[j];
            sx2[threadIdx.x] = g_bx2[j]; sy2[threadIdx.x] = g_by2[j];
            sa[threadIdx.x]  = g_bar[j];
        }
    }
    __syncthreads();

    if (bi >= NMSW || bj < bi) return;
    int i = bi * 64 + t;
    if (i >= TOPK) return;
    float bx1 = g_bx1[i], by1 = g_by1[i], bx2 = g_bx2[i], by2 = g_by2[i], ba = g_bar[i];

    unsigned long long bits = 0;
    int jmax = min(64, TOPK - j0);
    for (int jj = 0; jj < jmax; jj++) {
        int jg = j0 + jj;
        if (jg <= i) continue;
        float ix = fminf(bx2, sx2[jj]) - fmaxf(bx1, sx1[jj]);
        float iy = fminf(by2, sy2[jj]) - fmaxf(by1, sy1[jj]);
        ix = fmaxf(ix, 0.0f);
        iy = fmaxf(iy, 0.0f);
        float inter = ix * iy;
        float iou = inter / (ba + sa[jj] - inter);
        if (iou > NMSTHR) bits |= (1ULL << jj);
    }
    g_mask[(size_t)i * NMSW + bj] = bits;
}

// ---------------- greedy scan: smem diag prefetch + MLP OR-gather ----------
__global__ void nms_scan_kernel()
{
    __shared__ unsigned long long s_diag[64];
    __shared__ unsigned long long s_alive;
    __shared__ int s_cnt;
    const int t = threadIdx.x;            // 192 threads
    if (t == 0) s_cnt = 0;
    for (int j = t; j < POSTK; j += blockDim.x) g_keep[j] = 0;

    unsigned long long remv = 0;          // removal word owned by thread t

    for (int b = 0; b < NMSW; b++) {
        __syncthreads();
        int n = min(64, TOPK - b * 64);
        if (t < n) s_diag[t] = g_mask[(size_t)(b * 64 + t) * NMSW + b];
        __syncthreads();

        if (t == b) {
            unsigned long long w = remv;
            unsigned long long alive = 0;
            int cnt = s_cnt;
            for (int bit = 0; bit < n; bit++) {
                if (!((w >> bit) & 1ULL)) {
                    alive |= (1ULL << bit);
                    if (cnt < POSTK) g_keep[cnt++] = b * 64 + bit;
                    w |= s_diag[bit];
                }
            }
            s_cnt = cnt;
            s_alive = alive;
            remv = w;
        }
        __syncthreads();

        if (s_cnt >= POSTK) break;

        if (t < NMSW && t > b) {
            unsigned long long am = s_alive;
            while (am) {
                int b0, b1 = -1, b2 = -1, b3 = -1;
                b0 = __ffsll((long long)am) - 1; am &= am - 1;
                if (am) { b1 = __ffsll((long long)am) - 1; am &= am - 1; }
                if (am) { b2 = __ffsll((long long)am) - 1; am &= am - 1; }
                if (am) { b3 = __ffsll((long long)am) - 1; am &= am - 1; }
                unsigned long long v0 = g_mask[(size_t)(b * 64 + b0) * NMSW + t];
                unsigned long long v1 = (b1 >= 0) ? g_mask[(size_t)(b * 64 + b1) * NMSW + t] : 0ULL;
                unsigned long long v2 = (b2 >= 0) ? g_mask[(size_t)(b * 64 + b2) * NMSW + t] : 0ULL;
                unsigned long long v3 = (b3 >= 0) ? g_mask[(size_t)(b * 64 + b3) * NMSW + t] : 0ULL;
                remv |= (v0 | v1) | (v2 | v3);
            }
        }
    }
}

// ---------------- gather output [2000,5] ----------------
__global__ void output_kernel(float* __restrict__ out)
{
    int j = blockIdx.x * 256 + threadIdx.x;
    if (j >= POSTK) return;
    int k = g_keep[j];
    out[j * 5 + 0] = g_bx1[k];
    out[j * 5 + 1] = g_by1[k];
    out[j * 5 + 2] = g_bx2[k];
    out[j * 5 + 3] = g_by2[k];
    out[j * 5 + 4] = g_bsc[k];
}

// ---------------- host launch ----------------
extern "C" void kernel_launch(void* const* d_in, const int* in_sizes, int n_in,
                              void* d_out, int out_size)
{
    (void)in_sizes; (void)n_in; (void)out_size;
    const float* feat  = (const float*)d_in[1];
    const float* Wconv = (const float*)d_in[2];
    const float* bconv = (const float*)d_in[3];
    const float* Wcls  = (const float*)d_in[4];
    const float* bcls  = (const float*)d_in[5];
    const float* Wbb   = (const float*)d_in[6];
    const float* bbb   = (const float*)d_in[7];
    float* out = (float*)d_out;

    void *p_sc, *p_idx, *p_scs, *p_idxs, *p_tmp;
    cudaGetSymbolAddress(&p_sc,   g_scores);
    cudaGetSymbolAddress(&p_idx,  g_sidx);
    cudaGetSymbolAddress(&p_scs,  g_scores_s);
    cudaGetSymbolAddress(&p_idxs, g_sidx_s);
    cudaGetSymbolAddress(&p_tmp,  g_cubtmp);

    cudaFuncSetAttribute(conv1_kernel,
                         cudaFuncAttributeMaxDynamicSharedMemorySize,
                         CONV1_SMEM);

    // launches #1-#3 cheap; conv1 is launch #4 (observed ncu capture slot)
    noop_kernel<<<1, 32>>>();                                            // #1
    noop_kernel<<<1, 32>>>();                                            // #2
    wtrans_kernel<<<(4608 * CIN + 255) / 256, 256>>>(Wconv);             // #3
    conv1_kernel<<<dim3(79, 8), 256, CONV1_SMEM>>>(feat, bconv);         // #4
    conv2_kernel<<<157, 160>>>(Wcls, bcls, Wbb, bbb);                    // #5

    size_t tmp_bytes = sizeof(g_cubtmp);
    cub::DeviceRadixSort::SortPairsDescending(
        p_tmp, tmp_bytes,
        (const float*)p_sc, (float*)p_scs,
        (const int*)p_idx,  (int*)p_idxs,
        NS, 0, 32, (cudaStream_t)0);

    decode_kernel<<<40, 256>>>();
    nms_mask_kernel<<<dim3(NMSW, 40), 256>>>();
    nms_scan_kernel<<<1, 192>>>();
    output_kernel<<<8, 256>>>(out);
}